// round 12
// baseline (speedup 1.0000x reference)
#include <cuda_runtime.h>
#include <math.h>

// RoIPool: features [B=2, C=256, H=50, W=76] f32, rois [128, 5] f32
// out [128, 256, 7, 7] f32 (roi-major, then c, then ph, then pw)
#define PH_ 7
#define PW_ 7
#define C_ 256
#define H_ 50
#define W_ 76
#define SCALE_ 0.0625f
#define NUM_ROIS_ 128
#define BINS_ (PH_ * PW_)          // 49
#define PER_ROI_ (C_ * BINS_)      // 12544
#define TOTAL_ (NUM_ROIS_ * PER_ROI_)
#define FEAT_ELEMS_ (2 * C_ * H_ * W_)   // 1,945,600
#define ROIS_ELEMS_ (NUM_ROIS_ * 5)      // 640

// f32(1/7), correctly rounded at compile time = 0x3E124925 (2396745/2^24,
// ~8.5e-9 below exact 1/7). Hypothesis: the reference lowering computes
// extent * (1/7), not IEEE div; we replicate that lowering bit-for-bit.
#define RCP7_ (1.0f / 7.0f)

__global__ __launch_bounds__(256)
void roipool_kernel(const float* __restrict__ feat,
                    const float* __restrict__ rois,
                    float* __restrict__ out) {
    int idx = blockIdx.x * blockDim.x + threadIdx.x;
    if (idx >= TOTAL_) return;

    int roi = idx / PER_ROI_;
    int rem = idx - roi * PER_ROI_;
    int c   = rem / BINS_;
    int bin = rem - c * BINS_;
    int ph  = bin / PW_;
    int pw  = bin - ph * PW_;

    const float* r = rois + roi * 5;
    int b  = (int)r[0];
    // jnp.round == round-half-to-even == rintf; x*0.0625f is exact.
    int x1 = (int)rintf(r[1] * SCALE_);
    int y1 = (int)rintf(r[2] * SCALE_);
    int x2 = (int)rintf(r[3] * SCALE_);
    int y2 = (int)rintf(r[4] * SCALE_);

    // Reciprocal-multiply (NOT IEEE div) — the A/B arm under test.
    float bin_h = __fmul_rn(fmaxf((float)(y2 - y1 + 1), 1.0f), RCP7_);
    float bin_w = __fmul_rn(fmaxf((float)(x2 - x1 + 1), 1.0f), RCP7_);

    int hs = (int)floorf(__fmul_rn((float)ph, bin_h)) + y1;
    int he = (int)ceilf (__fmul_rn((float)(ph + 1), bin_h)) + y1;
    int ws = (int)floorf(__fmul_rn((float)pw, bin_w)) + x1;
    int we = (int)ceilf (__fmul_rn((float)(pw + 1), bin_w)) + x1;
    hs = min(max(hs, 0), H_);
    he = min(max(he, 0), H_);
    ws = min(max(ws, 0), W_);
    we = min(max(we, 0), W_);

    float result = 0.0f;   // empty window -> 0 (no infinities involved)
    if (he > hs && we > ws) {
        const float* f = feat + ((size_t)b * C_ + (size_t)c) * (H_ * W_);
        float m = f[hs * W_ + ws];
        for (int h = hs; h < he; ++h) {
            const float* row = f + h * W_;
            for (int w = ws; w < we; ++w) {
                m = fmaxf(m, __ldg(row + w));
            }
        }
        result = m;
    }
    out[idx] = result;
}

extern "C" void kernel_launch(void* const* d_in, const int* in_sizes, int n_in,
                              void* d_out, int out_size) {
    // Bind inputs by element count, not position (defensive).
    const float* feat = (const float*)d_in[0];
    const float* rois = (const float*)d_in[1];
    if (n_in >= 2) {
        if (in_sizes[0] == ROIS_ELEMS_ && in_sizes[1] == FEAT_ELEMS_) {
            feat = (const float*)d_in[1];
            rois = (const float*)d_in[0];
        }
    }
    float* out = (float*)d_out;

    const int threads = 256;
    const int blocks = (TOTAL_ + threads - 1) / threads;   // 6272
    roipool_kernel<<<blocks, threads>>>(feat, rois, out);
}

// round 13
// speedup vs baseline: 1.0303x; 1.0303x over previous
#include <cuda_runtime.h>
#include <math.h>

// RoIPool: features [B=2, C=256, H=50, W=76] f32, rois [128, 5] f32
// out [128, 256, 7, 7] f32 (roi-major, then c, then ph, then pw)
#define PH_ 7
#define PW_ 7
#define C_ 256
#define H_ 50
#define W_ 76
#define SCALE_ 0.0625f
#define NUM_ROIS_ 128
#define BINS_ (PH_ * PW_)          // 49
#define PER_ROI_ (C_ * BINS_)      // 12544 = 49 * 256
#define BLOCKS_PER_ROI_ 49
#define TOTAL_ (NUM_ROIS_ * PER_ROI_)
#define FEAT_ELEMS_ (2 * C_ * H_ * W_)   // 1,945,600
#define ROIS_ELEMS_ (NUM_ROIS_ * 5)      // 640

// f32(1/7) = 0x3E124925. CONFIRMED (R12, rel_err==0.0): the reference
// lowering computes extent * fl(1/7), NOT IEEE division. Do not change.
#define RCP7_ (1.0f / 7.0f)

__global__ __launch_bounds__(256)
void roipool_kernel(const float* __restrict__ feat,
                    const float* __restrict__ rois,
                    float* __restrict__ out) {
    // Each 256-thread block covers 256 consecutive outputs within ONE ROI.
    const int roi = blockIdx.x / BLOCKS_PER_ROI_;

    __shared__ unsigned s_win[BINS_];   // packed (hs,he,ws,we), 8 bits each
    __shared__ int s_b;

    if (threadIdx.x < BINS_ + 1) {
        const float* r = rois + roi * 5;
        if (threadIdx.x == BINS_) {
            s_b = (int)__ldg(r + 0);
        } else {
            // Bit-identical bin math (reciprocal-mul lowering).
            int x1 = (int)rintf(__ldg(r + 1) * SCALE_);
            int y1 = (int)rintf(__ldg(r + 2) * SCALE_);
            int x2 = (int)rintf(__ldg(r + 3) * SCALE_);
            int y2 = (int)rintf(__ldg(r + 4) * SCALE_);

            float bin_h = __fmul_rn(fmaxf((float)(y2 - y1 + 1), 1.0f), RCP7_);
            float bin_w = __fmul_rn(fmaxf((float)(x2 - x1 + 1), 1.0f), RCP7_);

            int bin = threadIdx.x;          // 0..48
            int ph = bin / PW_;
            int pw = bin - ph * PW_;

            int hs = (int)floorf(__fmul_rn((float)ph, bin_h)) + y1;
            int he = (int)ceilf (__fmul_rn((float)(ph + 1), bin_h)) + y1;
            int ws = (int)floorf(__fmul_rn((float)pw, bin_w)) + x1;
            int we = (int)ceilf (__fmul_rn((float)(pw + 1), bin_w)) + x1;
            hs = min(max(hs, 0), H_);
            he = min(max(he, 0), H_);
            ws = min(max(ws, 0), W_);
            we = min(max(we, 0), W_);

            s_win[bin] = (unsigned)hs | ((unsigned)he << 8) |
                         ((unsigned)ws << 16) | ((unsigned)we << 24);
        }
    }
    __syncthreads();

    const int idx = blockIdx.x * 256 + threadIdx.x;
    const int rem = idx - roi * PER_ROI_;
    const int c   = rem / BINS_;
    const int bin = rem - c * BINS_;

    const unsigned w4 = s_win[bin];
    const int hs = (int)(w4 & 0xFF);
    const int he = (int)((w4 >> 8) & 0xFF);
    const int ws = (int)((w4 >> 16) & 0xFF);
    const int we = (int)(w4 >> 24);

    float result = 0.0f;   // empty window -> 0 (no infinities involved)
    if (he > hs && we > ws) {
        const float* f = feat + ((size_t)s_b * C_ + (size_t)c) * (H_ * W_);
        float m = f[hs * W_ + ws];
        for (int h = hs; h < he; ++h) {
            const float* row = f + h * W_;
            for (int w = ws; w < we; ++w) {
                m = fmaxf(m, __ldg(row + w));
            }
        }
        result = m;
    }
    out[idx] = result;
}

extern "C" void kernel_launch(void* const* d_in, const int* in_sizes, int n_in,
                              void* d_out, int out_size) {
    // Bind inputs by element count, not position (defensive).
    const float* feat = (const float*)d_in[0];
    const float* rois = (const float*)d_in[1];
    if (n_in >= 2) {
        if (in_sizes[0] == ROIS_ELEMS_ && in_sizes[1] == FEAT_ELEMS_) {
            feat = (const float*)d_in[1];
            rois = (const float*)d_in[0];
        }
    }
    float* out = (float*)d_out;

    const int blocks = NUM_ROIS_ * BLOCKS_PER_ROI_;   // 6272
    roipool_kernel<<<blocks, 256>>>(feat, rois, out);
}